// round 15
// baseline (speedup 1.0000x reference)
#include <cuda_runtime.h>

#define C_IN   64
#define C_OUT  128
#define NKER   16
#define BEV_H  512
#define BEV_W  512
#define HW     (BEV_H * BEV_W)
#define MAXN   65536
#define NBX    1024        // (b,x) bins
#define CAPX   1024        // max points per (b,x) bin (fixed region)
#define CG     4           // channels per k_bev block
#define NCG    (C_OUT / CG)               // 32
#define ZPITCH 5           // z-major tile pitch: 4 ch + 1 pad

// ---------------- scratch (__device__ globals; no allocation) ----------------
// Zero-initialized at load; k_bev's done-counter resets cursors after the
// last consumer of each bin, so every graph replay starts from zeroed state.
__device__ int d_curX[NBX];
__device__ int d_doneX[NBX];
__device__ int d_binX[NBX * CAPX];       // packed (pt << 13) | (h << 9) | z

// ---------------------------------------------------------------------------
// Binning: bare spread-atomic scatter into fixed bin regions. Triggers PDL
// completion first so k_bev's Ks-preload phase overlaps this kernel.
// ---------------------------------------------------------------------------
__global__ __launch_bounds__(256)
void k_bin(const int* __restrict__ coords, int n)
{
    cudaTriggerProgrammaticLaunchCompletion();
    int i = blockIdx.x * 256 + threadIdx.x;
    if (i < n) {
        int4 c = ((const int4*)coords)[i];           // [x, h, z, b]
        int bx = (c.w << 9) | c.x;
        int slot = atomicAdd(&d_curX[bx], 1);
        if (slot < CAPX)
            d_binX[bx * CAPX + slot] = (i << 13) | ((c.y & (NKER - 1)) << 9) | c.z;
    }
}

// ---------------------------------------------------------------------------
// Fused GEMV + row-owner scatter. Block = (channel group of 4, bin (b,x)).
// smem: Ks[c][h][4] slice of the kernel for ALL 16 h (16 KB) + z-major tile
// [512][5] (10.3 KB) -> 8 blocks/SM, full occupancy.
//
// Before gridsync (overlaps k_bin): stage Ks, init zmask.
// Pass 1: mark touched z, zero touched tile cells.
// Pass 2: per point (4-lane group), GEMV its 4 channels directly from feats
//         (64 FFMA/lane, Ks LDS mostly broadcast/conflict-light), smem
//         atomicAdd into tile.
// Readout: R13 style — branch around LDS only, stores UNCONDITIONAL,
//          coalesced streaming STG.128. Covers every output element.
// Done-counter: 32nd finisher of a bin resets curX/doneX.
// ---------------------------------------------------------------------------
__global__ __launch_bounds__(256)
void k_bev(const float* __restrict__ feats,
           const float* __restrict__ kern,
           float* __restrict__ out)
{
    __shared__ float Ks[C_IN * NKER * CG];           // [c][h][q], 16 KB
    __shared__ float tile[512 * ZPITCH];             // 10.3 KB
    __shared__ unsigned int zmask[16];               // 512 bits

    const int bin = blockIdx.y;
    const int c0  = blockIdx.x << 2;
    const int b   = bin >> 9;
    const int x   = bin & 511;
    const int tid = threadIdx.x;
    const int grp = tid >> 2;                        // 0..63 (4-lane groups)
    const int ql  = tid & 3;

    // stage Ks: Ks[c*64 + h*4 + q] = kern[h][c][c0+q]  (runs during k_bin)
    for (int i = tid; i < C_IN * NKER * CG; i += 256) {
        int c = i >> 6;
        int h = (i >> 2) & (NKER - 1);
        int q = i & 3;
        Ks[i] = kern[h * (C_IN * C_OUT) + c * C_OUT + c0 + q];
    }
    if (tid < 16) zmask[tid] = 0u;

    cudaGridDependencySynchronize();                 // wait for k_bin
    __syncthreads();

    int cnt = d_curX[bin];
    if (cnt > CAPX) cnt = CAPX;
    const int* binp = d_binX + bin * CAPX;

    // pass 1: mark touched z + zero touched cells (races write 0 -> benign)
    for (int p = grp; p < cnt; p += 64) {
        int z = binp[p] & 511;
        if (ql == 0) atomicOr(&zmask[z >> 5], 1u << (z & 31));
        tile[z * ZPITCH + ql] = 0.f;
    }
    __syncthreads();

    // pass 2: GEMV this block's 4 channels for each point, accumulate
    for (int p = grp; p < cnt; p += 64) {
        int e  = binp[p];
        int z  = e & 511;
        int h  = (e >> 9) & (NKER - 1);
        int pt = e >> 13;
        const float4* f4 = (const float4*)(feats + (size_t)pt * C_IN);
        const float*  kq = Ks + h * 4 + ql;
        float acc = 0.f;
        #pragma unroll
        for (int t = 0; t < 16; t++) {
            float4 f = f4[t];
            acc += f.x * kq[(4 * t    ) * 64];
            acc += f.y * kq[(4 * t + 1) * 64];
            acc += f.z * kq[(4 * t + 2) * 64];
            acc += f.w * kq[(4 * t + 3) * 64];
        }
        atomicAdd(&tile[z * ZPITCH + ql], acc);
    }
    __syncthreads();

    // readout: thread owns chunk j for channels cb, cb+2 (stores unconditional)
    float4* o4 = (float4*)(out + (((size_t)(b * C_OUT + c0)) * BEV_H + x) * BEV_W);
    const int j  = tid & 127;                        // 4-z chunk
    const int cb = tid >> 7;                         // 0 or 1
    const unsigned int bits = (zmask[j >> 3] >> ((j & 7) * 4)) & 0xFu;
    const int zb = 4 * j;
    #pragma unroll
    for (int k = 0; k < 2; k++) {
        const int c = cb + 2 * k;
        float4 v = make_float4(0.f, 0.f, 0.f, 0.f);
        if (bits) {
            if (bits & 1u) v.x = tile[(zb    ) * ZPITCH + c];
            if (bits & 2u) v.y = tile[(zb + 1) * ZPITCH + c];
            if (bits & 4u) v.z = tile[(zb + 2) * ZPITCH + c];
            if (bits & 8u) v.w = tile[(zb + 3) * ZPITCH + c];
        }
        __stcs(&o4[(size_t)c * (HW / 4) + j], v);
    }

    // last of this bin's 32 blocks resets its cursors (all have read cnt)
    if (tid == 0) {
        int dn = atomicAdd(&d_doneX[bin], 1);
        if (dn == NCG - 1) { d_curX[bin] = 0; d_doneX[bin] = 0; }
    }
}

// ---------------------------------------------------------------------------
// Launch (PDL: k_bin -> fused k_bev)
// ---------------------------------------------------------------------------
extern "C" void kernel_launch(void* const* d_in, const int* in_sizes, int n_in,
                              void* d_out, int out_size)
{
    const int*   coords = (const int*)  d_in[0];   // [N,4] int32
    const float* feats  = (const float*)d_in[1];   // [N,64] f32
    const float* kern   = (const float*)d_in[2];   // [16,64,128] f32
    float*       out    = (float*)d_out;           // [2,128,512,512] f32

    int n = in_sizes[0] / 4;
    if (n > MAXN) n = MAXN;

    k_bin<<<(n + 255) / 256, 256>>>(coords, n);

    cudaLaunchAttribute attrs[1];
    attrs[0].id = cudaLaunchAttributeProgrammaticStreamSerialization;
    attrs[0].val.programmaticStreamSerializationAllowed = 1;

    cudaLaunchConfig_t cfg = {};
    cfg.gridDim  = dim3(NCG, NBX);
    cfg.blockDim = dim3(256);
    cfg.stream   = 0;
    cfg.attrs    = attrs;
    cfg.numAttrs = 1;
    cudaLaunchKernelEx(&cfg, k_bev, feats, kern, out);
}

// round 16
// speedup vs baseline: 3.8657x; 3.8657x over previous
#include <cuda_runtime.h>

#define C_IN   64
#define C_OUT  128
#define NKER   16
#define BEV_H  512
#define BEV_W  512
#define HW     (BEV_H * BEV_W)
#define MAXN   65536
#define NBX    1024        // (b,x) bins
#define CAPX   1024        // max points per (b,x) bin (fixed region)
#define PPB    64          // points per chunk, phase 1
#define FBLK   40          // k_feat blocks per h bin (grid-strided)
#define CG     8           // channels per k_bev block
#define NCG    (C_OUT / CG)
#define ZPITCH 9           // z-major tile pitch (floats): 8 ch + 1 pad

// ---------------- scratch (__device__ globals; no allocation) ----------------
// Zero-initialized at load; k_bev's done-counter resets ALL cursors after the
// last consumer of each bin, so every graph replay starts from zeroed state.
__device__ int   d_curH[NKER];
__device__ int   d_curX[NBX];
__device__ int   d_doneX[NBX];
__device__ int   d_binH[NKER * MAXN];            // point index, region per h
__device__ int   d_binX[NBX * CAPX];             // packed (pt << 9) | z
__device__ float d_fbuf[(size_t)MAXN * C_OUT];   // per-point features post-GEMM

// ---------------- packed f32x2 helpers ----------------
__device__ __forceinline__ unsigned long long pack2(float lo, float hi) {
    unsigned long long r;
    asm("mov.b64 %0, {%1, %2};" : "=l"(r) : "f"(lo), "f"(hi));
    return r;
}
__device__ __forceinline__ void unpack2(unsigned long long v, float& lo, float& hi) {
    asm("mov.b64 {%0, %1}, %2;" : "=f"(lo), "=f"(hi) : "l"(v));
}
__device__ __forceinline__ unsigned long long fma2(unsigned long long a,
                                                   unsigned long long b,
                                                   unsigned long long c) {
    unsigned long long d;
    asm("fma.rn.f32x2 %0, %1, %2, %3;" : "=l"(d) : "l"(a), "l"(b), "l"(c));
    return d;
}

// ---------------------------------------------------------------------------
// Fused binning: 512 threads x 2 points/thread. Block-level smem histogram +
// rank, one reservation per non-empty bin per block, direct scatter.
// ---------------------------------------------------------------------------
__global__ __launch_bounds__(512)
void k_bin(const int* __restrict__ coords, int n)
{
    __shared__ int histH[NKER],  baseH[NKER];
    __shared__ int histX[NBX],   baseX[NBX];

    const int tid = threadIdx.x;
    if (tid < 256) {
        int4* h4 = (int4*)histX;
        h4[tid] = make_int4(0, 0, 0, 0);
    }
    if (tid < NKER) histH[tid] = 0;
    __syncthreads();

    int  idx[2];
    int  h[2], bx[2], z[2], rH[2], rX[2];
    bool valid[2];
    #pragma unroll
    for (int s = 0; s < 2; s++) {
        int i = blockIdx.x * 1024 + s * 512 + tid;
        idx[s] = i;
        valid[s] = (i < n);
        if (valid[s]) {
            int4 c = ((const int4*)coords)[i];       // [x, h, z, b]
            h[s]  = c.y & (NKER - 1);
            bx[s] = (c.w << 9) | c.x;
            z[s]  = c.z;
            rH[s] = atomicAdd(&histH[h[s]], 1);
            rX[s] = atomicAdd(&histX[bx[s]], 1);
        }
    }
    __syncthreads();

    if (tid < NKER && histH[tid] > 0)
        baseH[tid] = atomicAdd(&d_curH[tid], histH[tid]);
    for (int j = tid; j < NBX; j += 512)
        if (histX[j] > 0)
            baseX[j] = atomicAdd(&d_curX[j], histX[j]);
    __syncthreads();

    #pragma unroll
    for (int s = 0; s < 2; s++) {
        if (valid[s]) {
            d_binH[h[s] * MAXN + baseH[h[s]] + rH[s]] = idx[s];
            int slot = baseX[bx[s]] + rX[s];
            if (slot < CAPX)
                d_binX[bx[s] * CAPX + slot] = (idx[s] << 9) | z[s];
        }
    }
    cudaTriggerProgrammaticLaunchCompletion();
}

// ---------------------------------------------------------------------------
// Phase 1: per-point GEMV  f_buf[pt][c] = feats[pt] . K[h][.][c]
// Grid (FBLK, NKER), grid-strided. Kernel slice staged into SMEM BEFORE the
// PDL grid sync, overlapping k_bin's tail.
// ---------------------------------------------------------------------------
__global__ __launch_bounds__(256)
void k_feat(const float* __restrict__ feats,
            const float* __restrict__ kern)
{
    const int bin = blockIdx.y;

    __shared__ float Ks[C_IN * C_OUT];               // 32 KB
    {
        const float4* g = (const float4*)(kern + (size_t)bin * C_IN * C_OUT);
        float4* sp = (float4*)Ks;
        for (int i = threadIdx.x; i < (C_IN * C_OUT) / 4; i += 256)
            sp[i] = g[i];
    }

    cudaGridDependencySynchronize();                 // wait for k_bin results
    __syncthreads();

    const int cnt = d_curH[bin];
    const int* binp = d_binH + bin * MAXN;
    const int warp = threadIdx.x >> 5;
    const int lane = threadIdx.x & 31;

    for (int bstart = blockIdx.x * PPB; bstart < cnt; bstart += FBLK * PPB) {
        const int bend = min(bstart + PPB, cnt);

        for (int g0 = bstart + warp * 4; g0 < bend; g0 += 32) {
            const int nv = min(4, bend - g0);
            float2 fv[4];
            int    pts[4];

            #pragma unroll
            for (int p = 0; p < 4; p++) {
                if (p < nv) {
                    pts[p] = binp[g0 + p];
                    fv[p]  = ((const float2*)(feats + (size_t)pts[p] * C_IN))[lane];
                } else {
                    fv[p] = make_float2(0.f, 0.f);
                    pts[p] = 0;
                }
            }

            unsigned long long accA[4], accB[4];
            #pragma unroll
            for (int p = 0; p < 4; p++) { accA[p] = 0ull; accB[p] = 0ull; }

            #pragma unroll
            for (int c = 0; c < C_IN; c++) {
                float4 k = *(const float4*)(Ks + c * C_OUT + 4 * lane);
                unsigned long long kA = pack2(k.x, k.y);
                unsigned long long kB = pack2(k.z, k.w);
                #pragma unroll
                for (int p = 0; p < 4; p++) {
                    float f = __shfl_sync(0xffffffffu,
                                          (c & 1) ? fv[p].y : fv[p].x, c >> 1);
                    unsigned long long ff = pack2(f, f);
                    accA[p] = fma2(ff, kA, accA[p]);
                    accB[p] = fma2(ff, kB, accB[p]);
                }
            }

            #pragma unroll
            for (int p = 0; p < 4; p++) {
                if (p < nv) {
                    float4 v;
                    unpack2(accA[p], v.x, v.y);
                    unpack2(accB[p], v.z, v.w);
                    *(float4*)(d_fbuf + (size_t)pts[p] * C_OUT + 4 * lane) = v;
                }
            }
        }
    }
    cudaTriggerProgrammaticLaunchCompletion();
}

// ---------------------------------------------------------------------------
// Phase 2: row-owner scatter with sparse z-major tile, 8 channels per block.
// Grid (NCG, NBX), 18.4 KB smem -> 8 blocks/SM, full occupancy.
// Pass 1 (zmask + touched-cell zeroing); gridsync; pass 2 smem-atomic adds.
// READOUT: hoisted index math (j, cb, nibble extracted once), ONE
// unconditional store stream (no divergent store duplication — R14 lesson),
// tile loads predicated per component.
// Done-counter: 16th finisher of a bin resets curX/doneX/curH.
// ---------------------------------------------------------------------------
__global__ __launch_bounds__(256)
void k_bev(float* __restrict__ out)
{
    __shared__ float tile[512 * ZPITCH];             // 18.4 KB
    __shared__ unsigned int zmask[16];               // 512 bits

    const int bin = blockIdx.y;
    const int c0  = blockIdx.x << 3;
    const int b   = bin >> 9;
    const int x   = bin & 511;
    const int tid  = threadIdx.x;
    const int qwid = tid >> 3;                       // 0..31
    const int ql   = tid & 7;

    if (tid < 16) zmask[tid] = 0u;
    __syncthreads();

    int cnt = d_curX[bin];
    if (cnt > CAPX) cnt = CAPX;
    const int* binp = d_binX + bin * CAPX;

    // pass 1: mark + zero touched cells (races write 0 -> benign)
    for (int p = qwid; p < cnt; p += 32) {
        int z = binp[p] & 511;
        if (ql == 0) atomicOr(&zmask[z >> 5], 1u << (z & 31));
        tile[z * ZPITCH + ql] = 0.f;
    }

    cudaGridDependencySynchronize();                 // wait for k_feat's f_buf
    __syncthreads();

    // pass 2: accumulate (quarter-warp = one point, lane = channel)
    for (int p = qwid; p < cnt; p += 32) {
        int e  = binp[p];
        int pt = e >> 9;
        int z  = e & 511;
        float v = d_fbuf[(size_t)pt * C_OUT + c0 + ql];
        atomicAdd(&tile[z * ZPITCH + ql], v);
    }
    __syncthreads();

    // readout: thread owns chunk j, channels cb+2k (k=0..3). Single store
    // stream; per-component predicated LDS; constant-stride addressing.
    const int j  = tid & 127;                        // 4-z chunk
    const int cb = tid >> 7;                         // 0 or 1
    const unsigned int bits = (zmask[j >> 3] >> ((j & 7) * 4)) & 0xFu;
    float4* obase = (float4*)(out + (((size_t)(b * C_OUT + c0 + cb)) * BEV_H + x) * BEV_W) + j;
    const size_t cstride = 2 * (size_t)(HW / 4);     // 2 channels in float4s
    const int zb = 4 * j;

    #pragma unroll
    for (int k = 0; k < 4; k++) {
        const int c = cb + 2 * k;
        float4 v = make_float4(0.f, 0.f, 0.f, 0.f);
        if (bits & 1u) v.x = tile[(zb    ) * ZPITCH + c];
        if (bits & 2u) v.y = tile[(zb + 1) * ZPITCH + c];
        if (bits & 4u) v.z = tile[(zb + 2) * ZPITCH + c];
        if (bits & 8u) v.w = tile[(zb + 3) * ZPITCH + c];
        __stcs(obase + (size_t)k * cstride, v);
    }

    // last of this bin's 16 blocks resets its cursors (all have read cnt,
    // and k_feat is fully complete past the gridsync above)
    if (tid == 0) {
        int dn = atomicAdd(&d_doneX[bin], 1);
        if (dn == NCG - 1) {
            d_curX[bin] = 0;
            d_doneX[bin] = 0;
            if (bin < NKER) d_curH[bin] = 0;
        }
    }
}

// ---------------------------------------------------------------------------
// Launch (PDL chain: k_bin -> k_feat -> k_bev)
// ---------------------------------------------------------------------------
extern "C" void kernel_launch(void* const* d_in, const int* in_sizes, int n_in,
                              void* d_out, int out_size)
{
    const int*   coords = (const int*)  d_in[0];   // [N,4] int32
    const float* feats  = (const float*)d_in[1];   // [N,64] f32
    const float* kern   = (const float*)d_in[2];   // [16,64,128] f32
    float*       out    = (float*)d_out;           // [2,128,512,512] f32

    int n = in_sizes[0] / 4;
    if (n > MAXN) n = MAXN;

    k_bin<<<(n + 1023) / 1024, 512>>>(coords, n);

    cudaLaunchAttribute attrs[1];
    attrs[0].id = cudaLaunchAttributeProgrammaticStreamSerialization;
    attrs[0].val.programmaticStreamSerializationAllowed = 1;

    {   // k_feat with PDL (smem preload overlaps k_bin tail)
        cudaLaunchConfig_t cfg = {};
        cfg.gridDim  = dim3(FBLK, NKER);
        cfg.blockDim = dim3(256);
        cfg.stream   = 0;
        cfg.attrs    = attrs;
        cfg.numAttrs = 1;
        cudaLaunchKernelEx(&cfg, k_feat, feats, kern);
    }
    {   // k_bev with PDL
        cudaLaunchConfig_t cfg = {};
        cfg.gridDim  = dim3(NCG, NBX);
        cfg.blockDim = dim3(256);
        cfg.stream   = 0;
        cfg.attrs    = attrs;
        cfg.numAttrs = 1;
        cudaLaunchKernelEx(&cfg, k_bev, out);
    }
}